// round 9
// baseline (speedup 1.0000x reference)
#include <cuda_runtime.h>
#include <cuda_bf16.h>
#include <cstddef>

// Problem constants
#define BB   1024   // batch
#define TT   336    // time steps
#define II   16     // input features
#define HH   64     // hidden
#define GG   256    // 4*H gates

// LSTM batch partition over all 148 SMs: 136 blocks x 7 rows + 12 blocks x 6 rows
#define LBLK  148
#define RMAX  7
#define NB7   136   // blocks with 7 rows; rest have 6

// Scratch (device globals: allocation inside kernel_launch is forbidden)
__device__ float g_xp[(size_t)TT * BB * GG];   // [T][B][4H] input-projection pre-activations
__device__ float g_h1[(size_t)TT * BB * HH];   // [T][B][H] layer-0 hidden outputs
__device__ float g_h2[(size_t)BB * HH];        // [B][H] layer-1 last hidden

// sigmoid via __expf: no cancellation anywhere in its range.
__device__ __forceinline__ float sigf(float x) { return 1.0f / (1.0f + __expf(-x)); }

// ---- packed f32x2 helpers (FFMA2: 2 lane-FMAs per issue slot; PTX-only path) ----
typedef unsigned long long u64;

__device__ __forceinline__ u64 pack2(float lo, float hi) {
    u64 r; asm("mov.b64 %0, {%1, %2};" : "=l"(r) : "f"(lo), "f"(hi)); return r;
}
__device__ __forceinline__ void unpack2(u64 v, float& lo, float& hi) {
    asm("mov.b64 {%0, %1}, %2;" : "=f"(lo), "=f"(hi) : "l"(v));
}
__device__ __forceinline__ u64 fma2(u64 a, u64 b, u64 c) {
    u64 d; asm("fma.rn.f32x2 %0, %1, %2, %3;" : "=l"(d) : "l"(a), "l"(b), "l"(c)); return d;
}
__device__ __forceinline__ float hsum2(u64 a) {
    float lo, hi; unpack2(a, lo, hi); return lo + hi;
}

// ---------------------------------------------------------------------------
// proj0: g_xp[t][b][g] = sum_i x[b][t][i] * Wih0[g][i] + bih0[g] + bhh0[g]
// 64 (t,b) pairs per block, 256 threads = one thread per gate g. K=16.
// ---------------------------------------------------------------------------
__global__ void __launch_bounds__(256) proj0_kernel(const float* __restrict__ x,
                                                    const float* __restrict__ Wih,
                                                    const float* __restrict__ bih,
                                                    const float* __restrict__ bhh) {
    __shared__ __align__(16) float xs[64][II];
    const int tid = threadIdx.x;
    const int g = tid;
    const float bsum = bih[g] + bhh[g];

    const int n0 = blockIdx.x * 64;  // linear (t,b) index: n = t*B + b
    for (int idx = tid; idx < 64 * II; idx += 256) {
        const int p = idx >> 4, i = idx & 15;
        const int n = n0 + p;
        const int t = n >> 10;        // n / 1024 (B=1024)
        const int b = n & 1023;
        xs[p][i] = x[((size_t)b * TT + t) * II + i];
    }
    // 16 weights -> 8 packed pairs in registers
    u64 w2[8];
    {
        const ulonglong2* Wv = reinterpret_cast<const ulonglong2*>(Wih + (size_t)g * II);
        #pragma unroll
        for (int k = 0; k < 4; ++k) { ulonglong2 v = Wv[k]; w2[2*k] = v.x; w2[2*k+1] = v.y; }
    }
    __syncthreads();

    #pragma unroll 4
    for (int p = 0; p < 64; ++p) {
        const ulonglong2* xv = reinterpret_cast<const ulonglong2*>(xs[p]);
        u64 accA = pack2(bsum, 0.0f), accB = pack2(0.0f, 0.0f);
        #pragma unroll
        for (int k = 0; k < 4; ++k) {
            ulonglong2 xx = xv[k];
            accA = fma2(xx.x, w2[2*k],   accA);
            accB = fma2(xx.y, w2[2*k+1], accB);
        }
        g_xp[(size_t)(n0 + p) * GG + g] = hsum2(accA) + hsum2(accB);
    }
}

// ---------------------------------------------------------------------------
// proj1: g_xp[t][b][g] = sum_j g_h1[t][b][j] * Wih1[g][j] + bih1[g] + bhh1[g]
// 64 (t,b) pairs per block, 256 threads = one thread per gate g. K=64.
// ---------------------------------------------------------------------------
#define P1P 64
__global__ void __launch_bounds__(256) proj1_kernel(const float* __restrict__ Wih,
                                                    const float* __restrict__ bih,
                                                    const float* __restrict__ bhh) {
    __shared__ __align__(16) float hs[P1P * HH];   // 16KB
    const int tid = threadIdx.x;
    const int g = tid;
    const float bsum = bih[g] + bhh[g];

    const int n0 = blockIdx.x * P1P;
    {
        const float4* src = reinterpret_cast<const float4*>(g_h1 + (size_t)n0 * HH);
        float4* dst = reinterpret_cast<float4*>(hs);
        #pragma unroll 4
        for (int idx = tid; idx < (P1P * HH) / 4; idx += 256) dst[idx] = src[idx];
    }
    // 64 weights -> 32 packed pairs in registers
    u64 w2[32];
    {
        const ulonglong2* Wv = reinterpret_cast<const ulonglong2*>(Wih + (size_t)g * HH);
        #pragma unroll
        for (int k = 0; k < 16; ++k) { ulonglong2 v = Wv[k]; w2[2*k] = v.x; w2[2*k+1] = v.y; }
    }
    __syncthreads();

    #pragma unroll 2
    for (int p = 0; p < P1P; ++p) {
        const ulonglong2* hv = reinterpret_cast<const ulonglong2*>(hs + p * HH);
        u64 accA = pack2(bsum, 0.0f), accB = pack2(0.0f, 0.0f);
        #pragma unroll
        for (int k = 0; k < 16; ++k) {
            ulonglong2 h2 = hv[k];
            accA = fma2(h2.x, w2[2*k],   accA);
            accB = fma2(h2.y, w2[2*k+1], accB);
        }
        g_xp[(size_t)(n0 + p) * GG + g] = hsum2(accA) + hsum2(accB);
    }
}

// ---------------------------------------------------------------------------
// LSTM recurrence, load-balanced over 148 SMs (7 rows/block, last 12 have 6),
// 512 threads, split-K:
// Phase 1: thread (g = tid&255, half = tid>>8) computes a K=32 partial of the
//          gate pre-activation for gate g across RMAX rows; weights (16 f32x2
//          pairs) in registers, h broadcast from shared via 128-bit LDS.
//          Partials land in gA (half 0, + xp[already incl. biases]) and gB.
// Phase 2: thread tid<448 owns exactly one (row, unit): loads all 8 gate
//          partials first (overlapped LDS), then activations (accurate tanhf),
//          updates c (register), h_s.
// xp prefetched 2 steps ahead from GMEM (~1.1k-cycle step >> DRAM latency).
// For 6-row blocks row 6 is a clamped phantom: gates computed, never consumed.
// Two barriers/step: H1 gates(write->read), H2 h(write->next-step read);
// provably minimal for the alternating RAW hazards between disjoint roles.
// ---------------------------------------------------------------------------
__global__ void __launch_bounds__(512, 1) lstm_kernel(const float* __restrict__ Whh,
                                                      int write_all) {
    __shared__ __align__(16) float h_s[RMAX * HH];   // 1.75KB
    __shared__ float gA[RMAX * GG];                  // 7KB
    __shared__ float gB[RMAX * GG];                  // 7KB
    const int tid = threadIdx.x;
    const int g = tid & 255;
    const int half = tid >> 8;
    const int bid = blockIdx.x;
    const int rows = (bid < NB7) ? 7 : 6;
    const int b0 = (bid < NB7) ? bid * 7 : NB7 * 7 + (bid - NB7) * 6;

    // per-row g_xp row offsets (phantom row clamped in-bounds)
    size_t rowoff[RMAX];
    #pragma unroll
    for (int b = 0; b < RMAX; ++b) {
        int rr = b0 + b; if (rr > BB - 1) rr = BB - 1;
        rowoff[b] = (size_t)rr * GG;
    }

    // this thread's K-half of the recurrent weights: 32 floats -> 16 pairs
    u64 w2[16];
    {
        const ulonglong2* Wv = reinterpret_cast<const ulonglong2*>(Whh + (size_t)g * HH + half * 32);
        #pragma unroll
        for (int k = 0; k < 8; ++k) { ulonglong2 v = Wv[k]; w2[2*k] = v.x; w2[2*k+1] = v.y; }
    }
    for (int idx = tid; idx < RMAX * HH; idx += 512) h_s[idx] = 0.0f;

    // phase-2 role: one (row, unit) per thread; base pointers hoisted
    const int r2 = tid >> 6;          // 0..7
    const int u2 = tid & 63;
    const bool p2 = (tid < RMAX * 64) && (r2 < rows);
    const float* const p2a = gA + (r2 < RMAX ? r2 : 0) * GG + u2;
    const float* const p2b = gB + (r2 < RMAX ? r2 : 0) * GG + u2;
    float* const p2h = h_s + (r2 < RMAX ? r2 : 0) * HH + u2;
    float* const p2g1 = g_h1 + (size_t)(b0 + r2) * HH + u2;   // + t*BB*HH per step
    float* const p2g2 = g_h2 + (size_t)(b0 + r2) * HH + u2;
    float c = 0.0f;

    const size_t stepStride = (size_t)BB * GG;      // 262144
    const float* xpp = g_xp + g;

    float xp_cur[RMAX], xp_nxt[RMAX];
    if (half == 0) {
        #pragma unroll
        for (int b = 0; b < RMAX; ++b) xp_cur[b] = xpp[rowoff[b]];
        #pragma unroll
        for (int b = 0; b < RMAX; ++b) xp_nxt[b] = xpp[stepStride + rowoff[b]];
    }

    float* const gOut = half ? gB : gA;
    const float* const hbase = h_s + half * 32;

    __syncthreads();

    #pragma unroll 1
    for (int t = 0; t < TT; ++t) {
        u64 acc[RMAX];
        if (half == 0) {
            #pragma unroll
            for (int b = 0; b < RMAX; ++b) acc[b] = pack2(xp_cur[b], 0.0f);
            #pragma unroll
            for (int b = 0; b < RMAX; ++b) xp_cur[b] = xp_nxt[b];
            if (t + 2 < TT) {
                const float* src = xpp + (size_t)(t + 2) * stepStride;
                #pragma unroll
                for (int b = 0; b < RMAX; ++b) xp_nxt[b] = src[rowoff[b]];
            }
        } else {
            #pragma unroll
            for (int b = 0; b < RMAX; ++b) acc[b] = pack2(0.0f, 0.0f);
        }

        // K=32 partial: acc[b] += sum_j h[b][half*32+j] * W[g][half*32+j]
        #pragma unroll
        for (int k = 0; k < 8; ++k) {
            const u64 wA = w2[2*k], wB = w2[2*k+1];
            #pragma unroll
            for (int b = 0; b < RMAX; ++b) {
                ulonglong2 h2 = *reinterpret_cast<const ulonglong2*>(hbase + b * HH + k * 4);
                acc[b] = fma2(h2.x, wA, acc[b]);
                acc[b] = fma2(h2.y, wB, acc[b]);
            }
        }
        #pragma unroll
        for (int b = 0; b < RMAX; ++b) gOut[b * GG + g] = hsum2(acc[b]);
        __syncthreads();   // H1: gates visible to phase 2

        // cell update: exactly one row per thread, c in a register.
        // All 8 LDS issued before any MUFU work so their latencies overlap.
        if (p2) {
            const float a0 = p2a[0],   b0v = p2b[0];
            const float a1 = p2a[64],  b1v = p2b[64];
            const float a2 = p2a[128], b2v = p2b[128];
            const float a3 = p2a[192], b3v = p2b[192];
            float iv = sigf(a0 + b0v);
            float fv = sigf(a1 + b1v);
            float gv = tanhf(a2 + b2v);
            float ov = sigf(a3 + b3v);
            float cn = fmaf(fv, c, iv * gv);
            c = cn;
            float hn = ov * tanhf(cn);
            *p2h = hn;
            if (write_all) p2g1[(size_t)t * BB * HH] = hn;
            else if (t == TT - 1) *p2g2 = hn;
        }
        __syncthreads();   // H2: h updated before next step's phase 1
    }
}

// ---------------------------------------------------------------------------
// FC: out[b] = dot(g_h2[b], Wfc) + bfc
// ---------------------------------------------------------------------------
__global__ void __launch_bounds__(128) fc_kernel(const float* __restrict__ Wfc,
                                                 const float* __restrict__ bfc,
                                                 float* __restrict__ out) {
    __shared__ float w_s[HH];
    const int tid = threadIdx.x;
    if (tid < HH) w_s[tid] = Wfc[tid];
    __syncthreads();
    const int b = blockIdx.x * 128 + tid;
    if (b < BB) {
        const float* hp = g_h2 + (size_t)b * HH;
        float a = bfc[0];
        #pragma unroll
        for (int j = 0; j < HH; ++j) a = fmaf(hp[j], w_s[j], a);
        out[b] = a;
    }
}

extern "C" void kernel_launch(void* const* d_in, const int* in_sizes, int n_in,
                              void* d_out, int out_size) {
    const float* x    = (const float*)d_in[0];
    const float* Wih0 = (const float*)d_in[1];
    const float* Whh0 = (const float*)d_in[2];
    const float* bih0 = (const float*)d_in[3];
    const float* bhh0 = (const float*)d_in[4];
    const float* Wih1 = (const float*)d_in[5];
    const float* Whh1 = (const float*)d_in[6];
    const float* bih1 = (const float*)d_in[7];
    const float* bhh1 = (const float*)d_in[8];
    const float* Wfc  = (const float*)d_in[9];
    const float* bfc  = (const float*)d_in[10];
    float* out = (float*)d_out;

    proj0_kernel<<<(TT * BB) / 64, 256>>>(x, Wih0, bih0, bhh0);
    lstm_kernel<<<LBLK, 512>>>(Whh0, /*write_all=*/1);
    proj1_kernel<<<(TT * BB) / P1P, 256>>>(Wih1, bih1, bhh1);
    lstm_kernel<<<LBLK, 512>>>(Whh1, /*write_all=*/0);
    fc_kernel<<<(BB + 127) / 128, 128>>>(Wfc, bfc, out);
}